// round 16
// baseline (speedup 1.0000x reference)
#include <cuda_runtime.h>
#include <cuda_fp16.h>
#include <cstdint>
#include <math.h>

#define BB 32
#define CC 1024
#define QQ 128
#define DD 256
#define FF 1024
#define MM (BB * CC)

// ---- scratch: device globals (no allocations allowed) ----
__device__ float g_m[BB * CC];
__device__ float g_qw[BB * QQ];
__device__ float g_cw[BB * CC];
__device__ float g_q2c[BB * DD];
__device__ __half g_a16[(size_t)MM * FF];     // att, fp16 (64 MB)
__device__ __half g_h16[(size_t)MM * FF];     // h,   fp16 (64 MB)
__device__ __half g_w1[FF * FF];              // W1 fp16
__device__ __half g_w2[FF * FF];              // W2 fp16

#define CP16(smem_b, gptr) \
    asm volatile("cp.async.cg.shared.global [%0], [%1], 16;" :: "r"(smem_b), "l"(gptr))

#define LDSM4(r0, r1, r2, r3, addr) \
    asm volatile("ldmatrix.sync.aligned.m8n8.x4.shared.b16 {%0,%1,%2,%3}, [%4];" \
        : "=r"(r0), "=r"(r1), "=r"(r2), "=r"(r3) : "r"(addr))

// ================= K0: qw[b,q]=q.wq ; cw[b,c]=c.wc =================
__global__ void k_dots(const float* __restrict__ q, const float* __restrict__ ctx,
                       const float* __restrict__ wq, const float* __restrict__ wc)
{
    int w = (blockIdx.x * blockDim.x + threadIdx.x) >> 5;
    int lane = threadIdx.x & 31;
    const int NQ = BB * QQ, NC = BB * CC;
    if (w < NQ) {
        const float* v = q + (size_t)w * DD;
        float s = 0.f;
        #pragma unroll
        for (int i = 0; i < DD / 32; i++) s = fmaf(v[lane + i * 32], wq[lane + i * 32], s);
        #pragma unroll
        for (int o = 16; o; o >>= 1) s += __shfl_xor_sync(0xffffffffu, s, o);
        if (!lane) g_qw[w] = s;
    } else if (w < NQ + NC) {
        int ww = w - NQ;
        const float* v = ctx + (size_t)ww * DD;
        float s = 0.f;
        #pragma unroll
        for (int i = 0; i < DD / 32; i++) s = fmaf(v[lane + i * 32], wc[lane + i * 32], s);
        #pragma unroll
        for (int o = 16; o; o >>= 1) s += __shfl_xor_sync(0xffffffffu, s, o);
        if (!lane) g_cw[ww] = s;
    }
}

// ============ K1: fused sim -> softmax -> c2q -> att seg0/1/2 fp16 ============
// smem (floats): Ph (fp16 P, 128x128 halfs, XOR-swizzled) @0 (8192f)
//   phase1 alias: Cs @0 (4224f), Qs @4224 (4224f)
//   Qs2 @8192 (8704f) | red @16896 (2176f) | rowm @19072 | rowiv @19200
#define K1_SMEM_FLOATS 19328
#define K1_SMEM_BYTES (K1_SMEM_FLOATS * 4)
__global__ void __launch_bounds__(256, 2) k_attn(
    const float* __restrict__ ctx, const float* __restrict__ question,
    const float* __restrict__ wm)
{
    extern __shared__ float sm[];
    __half* Ph   = (__half*)sm;          // [row=q 0..127][128 halfs], chunk-swizzled
    float* Cs    = sm;                    // phase-1 alias
    float* Qs    = sm + 4224;
    float* Qs2   = sm + 8192;
    float* red   = sm + 16896;
    float* rowm  = sm + 19072;
    float* rowiv = sm + 19200;

    const int b = blockIdx.y, c0 = blockIdx.x << 7;
    const int tid = threadIdx.x, tx = tid & 15, ty = tid >> 4;
    const float* ctxb = ctx + ((size_t)b * CC + c0) * DD;
    const float* qb   = question + (size_t)b * QQ * DD;

    float acc[8][8];
    #pragma unroll
    for (int i = 0; i < 8; i++)
        #pragma unroll
        for (int j = 0; j < 8; j++) acc[i][j] = 0.f;

    // ---- phase 1: sim = ctx_tile @ (question*wm)^T (exact fp32) ----
    for (int dc = 0; dc < DD; dc += 32) {
        #pragma unroll
        for (int i = 0; i < 4; i++) {
            int idx = tid + (i << 8);
            int row = idx >> 3, kk = (idx & 7) << 2;
            float4 v = *(const float4*)(ctxb + (size_t)row * DD + dc + kk);
            Cs[(kk + 0) * 132 + row] = v.x;
            Cs[(kk + 1) * 132 + row] = v.y;
            Cs[(kk + 2) * 132 + row] = v.z;
            Cs[(kk + 3) * 132 + row] = v.w;
            float4 u  = *(const float4*)(qb + (size_t)row * DD + dc + kk);
            float4 w4 = *(const float4*)(wm + dc + kk);
            Qs[(kk + 0) * 132 + row] = u.x * w4.x;
            Qs[(kk + 1) * 132 + row] = u.y * w4.y;
            Qs[(kk + 2) * 132 + row] = u.z * w4.z;
            Qs[(kk + 3) * 132 + row] = u.w * w4.w;
        }
        __syncthreads();
        #pragma unroll 8
        for (int k = 0; k < 32; k++) {
            float4 a0 = *(const float4*)&Cs[k * 132 + (ty << 3)];
            float4 a1 = *(const float4*)&Cs[k * 132 + (ty << 3) + 4];
            float4 b0 = *(const float4*)&Qs[k * 132 + (tx << 3)];
            float4 b1 = *(const float4*)&Qs[k * 132 + (tx << 3) + 4];
            float ar[8] = {a0.x, a0.y, a0.z, a0.w, a1.x, a1.y, a1.z, a1.w};
            float br[8] = {b0.x, b0.y, b0.z, b0.w, b1.x, b1.y, b1.z, b1.w};
            #pragma unroll
            for (int i = 0; i < 8; i++)
                #pragma unroll
                for (int j = 0; j < 8; j++)
                    acc[i][j] = fmaf(ar[i], br[j], acc[i][j]);
        }
        __syncthreads();
    }

    // ---- phase 2: biases, rowmax (saved), softmax ----
    float cb[8], qbv[8];
    #pragma unroll
    for (int i = 0; i < 8; i++) cb[i] = g_cw[b * CC + c0 + (ty << 3) + i];
    #pragma unroll
    for (int j = 0; j < 8; j++) qbv[j] = g_qw[b * QQ + (tx << 3) + j];
    #pragma unroll
    for (int i = 0; i < 8; i++)
        #pragma unroll
        for (int j = 0; j < 8; j++) acc[i][j] += cb[i] + qbv[j];

    #pragma unroll
    for (int i = 0; i < 8; i++) {
        float m = acc[i][0];
        #pragma unroll
        for (int j = 1; j < 8; j++) m = fmaxf(m, acc[i][j]);
        red[((ty << 3) + i) * 17 + tx] = m;
    }
    __syncthreads();
    if (tid < 128) {
        float m = red[tid * 17];
        #pragma unroll
        for (int t = 1; t < 16; t++) m = fmaxf(m, red[tid * 17 + t]);
        rowm[tid] = m;
        g_m[b * CC + c0 + tid] = m;
    }
    __syncthreads();
    #pragma unroll
    for (int i = 0; i < 8; i++) {
        float rm = rowm[(ty << 3) + i];
        float s = 0.f;
        #pragma unroll
        for (int j = 0; j < 8; j++) { acc[i][j] = expf(acc[i][j] - rm); s += acc[i][j]; }
        red[((ty << 3) + i) * 17 + tx] = s;
    }
    __syncthreads();
    if (tid < 128) {
        float s = 0.f;
        #pragma unroll
        for (int t = 0; t < 16; t++) s += red[tid * 17 + t];
        rowiv[tid] = 1.0f / s;
    }
    __syncthreads();
    // store P fp16, row = q = tx*8+j, cols ty*8..+7, chunk-swizzled (chunk = ty ^ (row>>3) = ty ^ tx)
    {
        float riv[8];
        #pragma unroll
        for (int i = 0; i < 8; i++) riv[i] = rowiv[(ty << 3) + i];
        const int chunk = (ty ^ tx) << 3;
        #pragma unroll
        for (int j = 0; j < 8; j++) {
            int row = (tx << 3) + j;
            __half hh[8];
            #pragma unroll
            for (int i = 0; i < 8; i++) hh[i] = __float2half_rn(acc[i][j] * riv[i]);
            *(uint4*)&Ph[(row << 7) + chunk] = *(uint4*)hh;
        }
    }
    __syncthreads();

    // ---- phase 3: c2q = P @ question; fused fp16 att writes (seg 0,1,2) ----
    for (int db = 0; db < DD; db += 64) {
        #pragma unroll
        for (int i = 0; i < 8; i++) {
            int idx = tid + (i << 8);
            int qrow = idx >> 4, c4 = (idx & 15) << 2;
            *(float4*)&Qs2[qrow * 68 + c4] = *(const float4*)(qb + (size_t)qrow * DD + db + c4);
        }
        __syncthreads();
        float o[8][4];
        #pragma unroll
        for (int i = 0; i < 8; i++)
            #pragma unroll
            for (int j = 0; j < 4; j++) o[i][j] = 0.f;
        #pragma unroll 4
        for (int qk = 0; qk < 128; qk++) {
            uint4 pv = *(const uint4*)&Ph[(qk << 7) + ((ty ^ (qk >> 3)) << 3)];
            const __half2* h2 = (const __half2*)&pv;
            float2 f0 = __half22float2(h2[0]), f1 = __half22float2(h2[1]);
            float2 f2 = __half22float2(h2[2]), f3 = __half22float2(h2[3]);
            float pr[8] = {f0.x, f0.y, f1.x, f1.y, f2.x, f2.y, f3.x, f3.y};
            float4 qv = *(const float4*)&Qs2[qk * 68 + (tx << 2)];
            #pragma unroll
            for (int i = 0; i < 8; i++) {
                o[i][0] = fmaf(pr[i], qv.x, o[i][0]);
                o[i][1] = fmaf(pr[i], qv.y, o[i][1]);
                o[i][2] = fmaf(pr[i], qv.z, o[i][2]);
                o[i][3] = fmaf(pr[i], qv.w, o[i][3]);
            }
        }
        #pragma unroll
        for (int i = 0; i < 8; i++) {
            float4 cv = *(const float4*)(ctxb + (size_t)((ty << 3) + i) * DD + db + (tx << 2));
            size_t rowg = (size_t)(b * CC + c0 + (ty << 3) + i);
            size_t base = rowg * FF + db + (tx << 2);
            __half h0[4], h1[4], h2v[4];
            h0[0] = __float2half_rn(cv.x); h0[1] = __float2half_rn(cv.y);
            h0[2] = __float2half_rn(cv.z); h0[3] = __float2half_rn(cv.w);
            h1[0] = __float2half_rn(o[i][0]); h1[1] = __float2half_rn(o[i][1]);
            h1[2] = __float2half_rn(o[i][2]); h1[3] = __float2half_rn(o[i][3]);
            h2v[0] = __float2half_rn(cv.x * o[i][0]); h2v[1] = __float2half_rn(cv.y * o[i][1]);
            h2v[2] = __float2half_rn(cv.z * o[i][2]); h2v[3] = __float2half_rn(cv.w * o[i][3]);
            *(uint64_t*)(g_a16 + base)       = *(uint64_t*)h0;
            *(uint64_t*)(g_a16 + base + 256) = *(uint64_t*)h1;
            *(uint64_t*)(g_a16 + base + 512) = *(uint64_t*)h2v;
        }
        __syncthreads();
    }
}

// ============ K2: q2c[b,d] = softmax_c(rowmax) . context ============
__global__ void k_q2c(const float* __restrict__ ctx)
{
    __shared__ float w[CC];
    __shared__ float red[256];
    const int b = blockIdx.x, tid = threadIdx.x;
    float lm = -1e30f;
    for (int c = tid; c < CC; c += 256) { float v = g_m[b * CC + c]; w[c] = v; lm = fmaxf(lm, v); }
    red[tid] = lm; __syncthreads();
    for (int s = 128; s > 0; s >>= 1) { if (tid < s) red[tid] = fmaxf(red[tid], red[tid + s]); __syncthreads(); }
    float mx = red[0]; __syncthreads();
    float ls = 0.f;
    for (int c = tid; c < CC; c += 256) { float e = expf(w[c] - mx); w[c] = e; ls += e; }
    red[tid] = ls; __syncthreads();
    for (int s = 128; s > 0; s >>= 1) { if (tid < s) red[tid] += red[tid + s]; __syncthreads(); }
    float inv = 1.0f / red[0]; __syncthreads();
    float accv = 0.f;
    const float* cb = ctx + (size_t)b * CC * DD + tid;
    for (int c = 0; c < CC; c++) accv = fmaf(w[c], cb[(size_t)c * DD], accv);
    g_q2c[b * DD + tid] = accv * inv;
}

// ============ prep: convert W to fp16 ============
__global__ void k_cvtw(const float* __restrict__ W, __half* __restrict__ H)
{
    int t = blockIdx.x * 256 + threadIdx.x;
    float4 v = *(const float4*)(W + (size_t)t * 4);
    __half h[4];
    h[0] = __float2half_rn(v.x); h[1] = __float2half_rn(v.y);
    h[2] = __float2half_rn(v.z); h[3] = __float2half_rn(v.w);
    *(uint64_t*)(H + (size_t)t * 4) = *(uint64_t*)h;
}

// ============ prep: att segment 3 = fp16(ctx * q2c) ============
__global__ void k_build_seg3(const float* __restrict__ ctx)
{
    int t = blockIdx.x * 256 + threadIdx.x;      // MM*64 threads, one float4 each
    int r  = t >> 6;
    int c4 = (t & 63) << 2;
    int bb = r >> 10;
    float4 cv = *(const float4*)(ctx + (size_t)r * DD + c4);
    float4 qv = *(const float4*)(g_q2c + bb * DD + c4);
    __half h[4];
    h[0] = __float2half_rn(cv.x * qv.x); h[1] = __float2half_rn(cv.y * qv.y);
    h[2] = __float2half_rn(cv.z * qv.z); h[3] = __float2half_rn(cv.w * qv.w);
    *(uint64_t*)(g_a16 + (size_t)r * FF + 768 + c4) = *(uint64_t*)h;
}

// ============ GEMM: fp16 mma + ldmatrix, 128x128 tile, 3-stage, 2 blk/SM ============
#define SROW 40
#define ST_BYTES 20480
#define GEMM_SMEM (3 * ST_BYTES)
#define NKT (FF / 32)

__device__ __forceinline__ void mma_f16(float* c, const uint32_t* a, uint32_t b0, uint32_t b1) {
    asm volatile(
        "mma.sync.aligned.m16n8k16.row.col.f32.f16.f16.f32 "
        "{%0,%1,%2,%3},{%4,%5,%6,%7},{%8,%9},{%0,%1,%2,%3};"
        : "+f"(c[0]), "+f"(c[1]), "+f"(c[2]), "+f"(c[3])
        : "r"(a[0]), "r"(a[1]), "r"(a[2]), "r"(a[3]), "r"(b0), "r"(b1));
}

template <int MODE>
__global__ void __launch_bounds__(256, 2) k_gemm(
    const __half* __restrict__ A_g, const __half* __restrict__ B_g,
    const float* __restrict__ bias, const int* __restrict__ mask,
    float* __restrict__ out)
{
    extern __shared__ uint16_t sm16[];
    const int tid = threadIdx.x, lane = tid & 31, wrp = tid >> 5;
    const int g = lane >> 2, t4 = lane & 3;
    const int wm0 = (wrp >> 1) << 5;
    const int wn0 = (wrp & 1) << 6;
    const int m0 = blockIdx.x << 7, n0 = blockIdx.y << 7;
    const int bb = m0 >> 10;

    float acc[2][8][4];
    #pragma unroll
    for (int i = 0; i < 2; i++)
        #pragma unroll
        for (int j = 0; j < 8; j++)
            #pragma unroll
            for (int l = 0; l < 4; l++) acc[i][j][l] = 0.f;

    const uint32_t sbase = (uint32_t)__cvta_generic_to_shared(sm16);
    const uint32_t aOff = (uint32_t)(((wm0 + (lane & 7) + (((lane >> 3) & 1) << 3)) * SROW
                                     + (((lane >> 4) & 1) << 3)) << 1);
    const uint32_t bOff = (uint32_t)(((wn0 + (lane & 7) + (((lane >> 4) & 1) << 3)) * SROW
                                     + (((lane >> 3) & 1) << 3)) << 1);

    auto load_stage = [&](int s, int kt) {
        const int k0 = kt << 5;
        const uint32_t sb = sbase + s * ST_BYTES;
        #pragma unroll
        for (int j = 0; j < 4; j++) {
            int v = tid + (j << 8);
            int arr = v >> 9;
            int mv = v & 511;
            int row = mv >> 2, q = mv & 3;
            uint32_t soff = sb + (uint32_t)arr * 10240u + (uint32_t)((row * SROW + q * 8) << 1);
            const __half* gp = (arr == 0)
                ? A_g + (size_t)(m0 + row) * FF + k0 + q * 8
                : B_g + (size_t)(n0 + row) * FF + k0 + q * 8;
            CP16(soff, gp);
        }
        asm volatile("cp.async.commit_group;");
    };

    load_stage(0, 0);
    load_stage(1, 1);

    for (int kt = 0; kt < NKT; kt++) {
        const int cur = kt % 3;
        if (kt + 1 < NKT) asm volatile("cp.async.wait_group 1;");
        else              asm volatile("cp.async.wait_group 0;");
        __syncthreads();
        if (kt + 2 < NKT) load_stage((kt + 2) % 3, kt + 2);

        const uint32_t stA = sbase + cur * ST_BYTES;
        const uint32_t stB = stA + 10240u;

        #pragma unroll
        for (int ks = 0; ks < 32; ks += 16) {
            uint32_t a[2][4];
            #pragma unroll
            for (int mt = 0; mt < 2; mt++) {
                uint32_t ad = stA + aOff + (uint32_t)(((mt * 16 * SROW) + ks) << 1);
                LDSM4(a[mt][0], a[mt][1], a[mt][2], a[mt][3], ad);
            }
            #pragma unroll
            for (int nf2 = 0; nf2 < 4; nf2++) {
                uint32_t bd = stB + bOff + (uint32_t)(((nf2 * 16 * SROW) + ks) << 1);
                uint32_t b0a, b1a, b0b, b1b;
                LDSM4(b0a, b1a, b0b, b1b, bd);
                mma_f16(acc[0][2 * nf2],     a[0], b0a, b1a);
                mma_f16(acc[1][2 * nf2],     a[1], b0a, b1a);
                mma_f16(acc[0][2 * nf2 + 1], a[0], b0b, b1b);
                mma_f16(acc[1][2 * nf2 + 1], a[1], b0b, b1b);
            }
        }
    }

    // epilogue
    #pragma unroll
    for (int mt = 0; mt < 2; mt++) {
        int r0 = m0 + wm0 + mt * 16 + g;
        float mv0 = mask[bb * CC + (r0 & 1023)] ? 1.f : 0.f;
        float mv1 = mask[bb * CC + ((r0 + 8) & 1023)] ? 1.f : 0.f;
        #pragma unroll
        for (int nf = 0; nf < 8; nf++) {
            int col = n0 + wn0 + nf * 8 + 2 * t4;
            float bz0 = bias[col], bz1 = bias[col + 1];
            float v00 = (acc[mt][nf][0] + bz0) * mv0;
            float v01 = (acc[mt][nf][1] + bz1) * mv0;
            float v10 = (acc[mt][nf][2] + bz0) * mv1;
            float v11 = (acc[mt][nf][3] + bz1) * mv1;
            size_t o0 = (size_t)r0 * FF + col;
            size_t o1 = (size_t)(r0 + 8) * FF + col;
            if (MODE == 0) {
                *(__half2*)(g_h16 + o0) = __floats2half2_rn(v00, v01);
                *(__half2*)(g_h16 + o1) = __floats2half2_rn(v10, v11);
            } else {
                *(float2*)&out[o0] = make_float2(fmaxf(v00, 0.f), fmaxf(v01, 0.f));
                *(float2*)&out[o1] = make_float2(fmaxf(v10, 0.f), fmaxf(v11, 0.f));
            }
        }
    }
}

// =========================== launch ===========================
extern "C" void kernel_launch(void* const* d_in, const int* in_sizes, int n_in,
                              void* d_out, int out_size)
{
    const float* ctx = (const float*)d_in[0];
    const float* qst = (const float*)d_in[1];
    const int*   mask = (const int*)d_in[2];     // bool promoted to int32
    const float* wq = (const float*)d_in[3];
    const float* wc = (const float*)d_in[4];
    const float* wm = (const float*)d_in[5];
    const float* W1 = (const float*)d_in[6];
    const float* b1 = (const float*)d_in[7];
    const float* W2 = (const float*)d_in[8];
    const float* b2 = (const float*)d_in[9];
    float* out = (float*)d_out;

    __half *w1, *w2, *a16, *h16;
    cudaGetSymbolAddress((void**)&w1,  g_w1);
    cudaGetSymbolAddress((void**)&w2,  g_w2);
    cudaGetSymbolAddress((void**)&a16, g_a16);
    cudaGetSymbolAddress((void**)&h16, g_h16);

    cudaFuncSetAttribute(k_attn, cudaFuncAttributeMaxDynamicSharedMemorySize, K1_SMEM_BYTES);
    cudaFuncSetAttribute(k_gemm<0>, cudaFuncAttributeMaxDynamicSharedMemorySize, GEMM_SMEM);
    cudaFuncSetAttribute(k_gemm<1>, cudaFuncAttributeMaxDynamicSharedMemorySize, GEMM_SMEM);

    k_cvtw<<<FF * FF / 4 / 256, 256>>>(W1, w1);
    k_cvtw<<<FF * FF / 4 / 256, 256>>>(W2, w2);

    int nwarps = BB * QQ + BB * CC;
    k_dots<<<(nwarps + 7) / 8, 256>>>(qst, ctx, wq, wc);
    k_attn<<<dim3(CC / 128, BB), 256, K1_SMEM_BYTES>>>(ctx, qst, wm);
    k_q2c<<<BB, 256>>>(ctx);
    k_build_seg3<<<MM * 64 / 256, 256>>>(ctx);

    k_gemm<0><<<dim3(MM / 128, FF / 128), 256, GEMM_SMEM>>>(a16, w1, b1, mask, nullptr);
    k_gemm<1><<<dim3(MM / 128, FF / 128), 256, GEMM_SMEM>>>(h16, w2, b2, mask, out);
}

// round 17
// speedup vs baseline: 1.0485x; 1.0485x over previous
#include <cuda_runtime.h>
#include <cuda_fp16.h>
#include <cstdint>
#include <math.h>

#define BB 32
#define CC 1024
#define QQ 128
#define DD 256
#define FF 1024
#define MM (BB * CC)

// ---- scratch: device globals (no allocations allowed) ----
__device__ float g_m[BB * CC];
__device__ float g_qw[BB * QQ];
__device__ float g_cw[BB * CC];
__device__ float g_q2c[BB * DD];
__device__ __half g_a16[(size_t)MM * FF];     // att, fp16 (64 MB)
__device__ __half g_h16[(size_t)MM * FF];     // h,   fp16 (64 MB)
__device__ __half g_w1[FF * FF];              // W1 fp16
__device__ __half g_w2[FF * FF];              // W2 fp16

#define CP16(smem_b, gptr) \
    asm volatile("cp.async.cg.shared.global [%0], [%1], 16;" :: "r"(smem_b), "l"(gptr))

#define LDSM4(r0, r1, r2, r3, addr) \
    asm volatile("ldmatrix.sync.aligned.m8n8.x4.shared.b16 {%0,%1,%2,%3}, [%4];" \
        : "=r"(r0), "=r"(r1), "=r"(r2), "=r"(r3) : "r"(addr))

// ================= K0: qw[b,q]=q.wq ; cw[b,c]=c.wc =================
__global__ void k_dots(const float* __restrict__ q, const float* __restrict__ ctx,
                       const float* __restrict__ wq, const float* __restrict__ wc)
{
    int w = (blockIdx.x * blockDim.x + threadIdx.x) >> 5;
    int lane = threadIdx.x & 31;
    const int NQ = BB * QQ, NC = BB * CC;
    if (w < NQ) {
        const float* v = q + (size_t)w * DD;
        float s = 0.f;
        #pragma unroll
        for (int i = 0; i < DD / 32; i++) s = fmaf(v[lane + i * 32], wq[lane + i * 32], s);
        #pragma unroll
        for (int o = 16; o; o >>= 1) s += __shfl_xor_sync(0xffffffffu, s, o);
        if (!lane) g_qw[w] = s;
    } else if (w < NQ + NC) {
        int ww = w - NQ;
        const float* v = ctx + (size_t)ww * DD;
        float s = 0.f;
        #pragma unroll
        for (int i = 0; i < DD / 32; i++) s = fmaf(v[lane + i * 32], wc[lane + i * 32], s);
        #pragma unroll
        for (int o = 16; o; o >>= 1) s += __shfl_xor_sync(0xffffffffu, s, o);
        if (!lane) g_cw[ww] = s;
    }
}

// ============ K1: fused sim -> softmax -> c2q -> att seg0/1/2 fp16 ============
#define K1_SMEM_FLOATS 19328
#define K1_SMEM_BYTES (K1_SMEM_FLOATS * 4)
__global__ void __launch_bounds__(256, 2) k_attn(
    const float* __restrict__ ctx, const float* __restrict__ question,
    const float* __restrict__ wm)
{
    extern __shared__ float sm[];
    __half* Ph   = (__half*)sm;          // [row=q 0..127][128 halfs], chunk-swizzled
    float* Cs    = sm;                    // phase-1 alias
    float* Qs    = sm + 4224;
    float* Qs2   = sm + 8192;
    float* red   = sm + 16896;
    float* rowm  = sm + 19072;
    float* rowiv = sm + 19200;

    const int b = blockIdx.y, c0 = blockIdx.x << 7;
    const int tid = threadIdx.x, tx = tid & 15, ty = tid >> 4;
    const float* ctxb = ctx + ((size_t)b * CC + c0) * DD;
    const float* qb   = question + (size_t)b * QQ * DD;

    float acc[8][8];
    #pragma unroll
    for (int i = 0; i < 8; i++)
        #pragma unroll
        for (int j = 0; j < 8; j++) acc[i][j] = 0.f;

    for (int dc = 0; dc < DD; dc += 32) {
        #pragma unroll
        for (int i = 0; i < 4; i++) {
            int idx = tid + (i << 8);
            int row = idx >> 3, kk = (idx & 7) << 2;
            float4 v = *(const float4*)(ctxb + (size_t)row * DD + dc + kk);
            Cs[(kk + 0) * 132 + row] = v.x;
            Cs[(kk + 1) * 132 + row] = v.y;
            Cs[(kk + 2) * 132 + row] = v.z;
            Cs[(kk + 3) * 132 + row] = v.w;
            float4 u  = *(const float4*)(qb + (size_t)row * DD + dc + kk);
            float4 w4 = *(const float4*)(wm + dc + kk);
            Qs[(kk + 0) * 132 + row] = u.x * w4.x;
            Qs[(kk + 1) * 132 + row] = u.y * w4.y;
            Qs[(kk + 2) * 132 + row] = u.z * w4.z;
            Qs[(kk + 3) * 132 + row] = u.w * w4.w;
        }
        __syncthreads();
        #pragma unroll 8
        for (int k = 0; k < 32; k++) {
            float4 a0 = *(const float4*)&Cs[k * 132 + (ty << 3)];
            float4 a1 = *(const float4*)&Cs[k * 132 + (ty << 3) + 4];
            float4 b0 = *(const float4*)&Qs[k * 132 + (tx << 3)];
            float4 b1 = *(const float4*)&Qs[k * 132 + (tx << 3) + 4];
            float ar[8] = {a0.x, a0.y, a0.z, a0.w, a1.x, a1.y, a1.z, a1.w};
            float br[8] = {b0.x, b0.y, b0.z, b0.w, b1.x, b1.y, b1.z, b1.w};
            #pragma unroll
            for (int i = 0; i < 8; i++)
                #pragma unroll
                for (int j = 0; j < 8; j++)
                    acc[i][j] = fmaf(ar[i], br[j], acc[i][j]);
        }
        __syncthreads();
    }

    float cb[8], qbv[8];
    #pragma unroll
    for (int i = 0; i < 8; i++) cb[i] = g_cw[b * CC + c0 + (ty << 3) + i];
    #pragma unroll
    for (int j = 0; j < 8; j++) qbv[j] = g_qw[b * QQ + (tx << 3) + j];
    #pragma unroll
    for (int i = 0; i < 8; i++)
        #pragma unroll
        for (int j = 0; j < 8; j++) acc[i][j] += cb[i] + qbv[j];

    #pragma unroll
    for (int i = 0; i < 8; i++) {
        float m = acc[i][0];
        #pragma unroll
        for (int j = 1; j < 8; j++) m = fmaxf(m, acc[i][j]);
        red[((ty << 3) + i) * 17 + tx] = m;
    }
    __syncthreads();
    if (tid < 128) {
        float m = red[tid * 17];
        #pragma unroll
        for (int t = 1; t < 16; t++) m = fmaxf(m, red[tid * 17 + t]);
        rowm[tid] = m;
        g_m[b * CC + c0 + tid] = m;
    }
    __syncthreads();
    #pragma unroll
    for (int i = 0; i < 8; i++) {
        float rm = rowm[(ty << 3) + i];
        float s = 0.f;
        #pragma unroll
        for (int j = 0; j < 8; j++) { acc[i][j] = expf(acc[i][j] - rm); s += acc[i][j]; }
        red[((ty << 3) + i) * 17 + tx] = s;
    }
    __syncthreads();
    if (tid < 128) {
        float s = 0.f;
        #pragma unroll
        for (int t = 0; t < 16; t++) s += red[tid * 17 + t];
        rowiv[tid] = 1.0f / s;
    }
    __syncthreads();
    {
        float riv[8];
        #pragma unroll
        for (int i = 0; i < 8; i++) riv[i] = rowiv[(ty << 3) + i];
        const int chunk = (ty ^ tx) << 3;
        #pragma unroll
        for (int j = 0; j < 8; j++) {
            int row = (tx << 3) + j;
            __half hh[8];
            #pragma unroll
            for (int i = 0; i < 8; i++) hh[i] = __float2half_rn(acc[i][j] * riv[i]);
            *(uint4*)&Ph[(row << 7) + chunk] = *(uint4*)hh;
        }
    }
    __syncthreads();

    for (int db = 0; db < DD; db += 64) {
        #pragma unroll
        for (int i = 0; i < 8; i++) {
            int idx = tid + (i << 8);
            int qrow = idx >> 4, c4 = (idx & 15) << 2;
            *(float4*)&Qs2[qrow * 68 + c4] = *(const float4*)(qb + (size_t)qrow * DD + db + c4);
        }
        __syncthreads();
        float o[8][4];
        #pragma unroll
        for (int i = 0; i < 8; i++)
            #pragma unroll
            for (int j = 0; j < 4; j++) o[i][j] = 0.f;
        #pragma unroll 4
        for (int qk = 0; qk < 128; qk++) {
            uint4 pv = *(const uint4*)&Ph[(qk << 7) + ((ty ^ (qk >> 3)) << 3)];
            const __half2* h2 = (const __half2*)&pv;
            float2 f0 = __half22float2(h2[0]), f1 = __half22float2(h2[1]);
            float2 f2 = __half22float2(h2[2]), f3 = __half22float2(h2[3]);
            float pr[8] = {f0.x, f0.y, f1.x, f1.y, f2.x, f2.y, f3.x, f3.y};
            float4 qv = *(const float4*)&Qs2[qk * 68 + (tx << 2)];
            #pragma unroll
            for (int i = 0; i < 8; i++) {
                o[i][0] = fmaf(pr[i], qv.x, o[i][0]);
                o[i][1] = fmaf(pr[i], qv.y, o[i][1]);
                o[i][2] = fmaf(pr[i], qv.z, o[i][2]);
                o[i][3] = fmaf(pr[i], qv.w, o[i][3]);
            }
        }
        #pragma unroll
        for (int i = 0; i < 8; i++) {
            float4 cv = *(const float4*)(ctxb + (size_t)((ty << 3) + i) * DD + db + (tx << 2));
            size_t rowg = (size_t)(b * CC + c0 + (ty << 3) + i);
            size_t base = rowg * FF + db + (tx << 2);
            __half h0[4], h1[4], h2v[4];
            h0[0] = __float2half_rn(cv.x); h0[1] = __float2half_rn(cv.y);
            h0[2] = __float2half_rn(cv.z); h0[3] = __float2half_rn(cv.w);
            h1[0] = __float2half_rn(o[i][0]); h1[1] = __float2half_rn(o[i][1]);
            h1[2] = __float2half_rn(o[i][2]); h1[3] = __float2half_rn(o[i][3]);
            h2v[0] = __float2half_rn(cv.x * o[i][0]); h2v[1] = __float2half_rn(cv.y * o[i][1]);
            h2v[2] = __float2half_rn(cv.z * o[i][2]); h2v[3] = __float2half_rn(cv.w * o[i][3]);
            *(uint64_t*)(g_a16 + base)       = *(uint64_t*)h0;
            *(uint64_t*)(g_a16 + base + 256) = *(uint64_t*)h1;
            *(uint64_t*)(g_a16 + base + 512) = *(uint64_t*)h2v;
        }
        __syncthreads();
    }
}

// ============ K2: q2c[b,d] = softmax_c(rowmax) . context ============
__global__ void k_q2c(const float* __restrict__ ctx)
{
    __shared__ float w[CC];
    __shared__ float red[256];
    const int b = blockIdx.x, tid = threadIdx.x;
    float lm = -1e30f;
    for (int c = tid; c < CC; c += 256) { float v = g_m[b * CC + c]; w[c] = v; lm = fmaxf(lm, v); }
    red[tid] = lm; __syncthreads();
    for (int s = 128; s > 0; s >>= 1) { if (tid < s) red[tid] = fmaxf(red[tid], red[tid + s]); __syncthreads(); }
    float mx = red[0]; __syncthreads();
    float ls = 0.f;
    for (int c = tid; c < CC; c += 256) { float e = expf(w[c] - mx); w[c] = e; ls += e; }
    red[tid] = ls; __syncthreads();
    for (int s = 128; s > 0; s >>= 1) { if (tid < s) red[tid] += red[tid + s]; __syncthreads(); }
    float inv = 1.0f / red[0]; __syncthreads();
    float accv = 0.f;
    const float* cb = ctx + (size_t)b * CC * DD + tid;
    for (int c = 0; c < CC; c++) accv = fmaf(w[c], cb[(size_t)c * DD], accv);
    g_q2c[b * DD + tid] = accv * inv;
}

// ============ prep: convert W to fp16 ============
__global__ void k_cvtw(const float* __restrict__ W, __half* __restrict__ H)
{
    int t = blockIdx.x * 256 + threadIdx.x;
    float4 v = *(const float4*)(W + (size_t)t * 4);
    __half h[4];
    h[0] = __float2half_rn(v.x); h[1] = __float2half_rn(v.y);
    h[2] = __float2half_rn(v.z); h[3] = __float2half_rn(v.w);
    *(uint64_t*)(H + (size_t)t * 4) = *(uint64_t*)h;
}

// ============ prep: att segment 3 = fp16(ctx * q2c) ============
__global__ void k_build_seg3(const float* __restrict__ ctx)
{
    int t = blockIdx.x * 256 + threadIdx.x;
    int r  = t >> 6;
    int c4 = (t & 63) << 2;
    int bb = r >> 10;
    float4 cv = *(const float4*)(ctx + (size_t)r * DD + c4);
    float4 qv = *(const float4*)(g_q2c + bb * DD + c4);
    __half h[4];
    h[0] = __float2half_rn(cv.x * qv.x); h[1] = __float2half_rn(cv.y * qv.y);
    h[2] = __float2half_rn(cv.z * qv.z); h[3] = __float2half_rn(cv.w * qv.w);
    *(uint64_t*)(g_a16 + (size_t)r * FF + 768 + c4) = *(uint64_t*)h;
}

// ============ GEMM: fp16 mma + ldmatrix, 128x128 tile, k64, 3-stage, 2 blk/SM ============
// stage (halfs, SROW=72): A[128*72] + B[128*72] = 36864B; x3 stages = 110592B
#define SROW 72
#define ARR_BYTES 18432
#define ST_BYTES 36864
#define GEMM_SMEM (3 * ST_BYTES)
#define NKT (FF / 64)

__device__ __forceinline__ void mma_f16(float* c, const uint32_t* a, uint32_t b0, uint32_t b1) {
    asm volatile(
        "mma.sync.aligned.m16n8k16.row.col.f32.f16.f16.f32 "
        "{%0,%1,%2,%3},{%4,%5,%6,%7},{%8,%9},{%0,%1,%2,%3};"
        : "+f"(c[0]), "+f"(c[1]), "+f"(c[2]), "+f"(c[3])
        : "r"(a[0]), "r"(a[1]), "r"(a[2]), "r"(a[3]), "r"(b0), "r"(b1));
}

template <int MODE>
__global__ void __launch_bounds__(256, 2) k_gemm(
    const __half* __restrict__ A_g, const __half* __restrict__ B_g,
    const float* __restrict__ bias, const int* __restrict__ mask,
    float* __restrict__ out)
{
    extern __shared__ uint16_t sm16[];
    const int tid = threadIdx.x, lane = tid & 31, wrp = tid >> 5;
    const int g = lane >> 2, t4 = lane & 3;
    const int wm0 = (wrp >> 1) << 5;
    const int wn0 = (wrp & 1) << 6;
    const int m0 = blockIdx.x << 7, n0 = blockIdx.y << 7;
    const int bb = m0 >> 10;

    float acc[2][8][4];
    #pragma unroll
    for (int i = 0; i < 2; i++)
        #pragma unroll
        for (int j = 0; j < 8; j++)
            #pragma unroll
            for (int l = 0; l < 4; l++) acc[i][j][l] = 0.f;

    const uint32_t sbase = (uint32_t)__cvta_generic_to_shared(sm16);
    const uint32_t aOff = (uint32_t)(((wm0 + (lane & 7) + (((lane >> 3) & 1) << 3)) * SROW
                                     + (((lane >> 4) & 1) << 3)) << 1);
    const uint32_t bOff = (uint32_t)(((wn0 + (lane & 7) + (((lane >> 4) & 1) << 3)) * SROW
                                     + (((lane >> 3) & 1) << 3)) << 1);

    auto load_stage = [&](int s, int kt) {
        const int k0 = kt << 6;
        const uint32_t sb = sbase + s * ST_BYTES;
        #pragma unroll
        for (int j = 0; j < 8; j++) {
            int v = tid + (j << 8);            // 0..2047 vec16 ids
            int arr = v >> 10;                 // 0=A 1=B
            int mv = v & 1023;
            int row = mv >> 3, q = mv & 7;     // 8 vec16 per row (64 halfs)
            uint32_t soff = sb + (uint32_t)arr * ARR_BYTES + (uint32_t)((row * SROW + q * 8) << 1);
            const __half* gp = (arr == 0)
                ? A_g + (size_t)(m0 + row) * FF + k0 + q * 8
                : B_g + (size_t)(n0 + row) * FF + k0 + q * 8;
            CP16(soff, gp);
        }
        asm volatile("cp.async.commit_group;");
    };

    load_stage(0, 0);
    load_stage(1, 1);

    for (int kt = 0; kt < NKT; kt++) {
        const int cur = kt % 3;
        if (kt + 1 < NKT) asm volatile("cp.async.wait_group 1;");
        else              asm volatile("cp.async.wait_group 0;");
        __syncthreads();
        if (kt + 2 < NKT) load_stage((kt + 2) % 3, kt + 2);

        const uint32_t stA = sbase + cur * ST_BYTES;
        const uint32_t stB = stA + (uint32_t)ARR_BYTES;

        #pragma unroll
        for (int ks = 0; ks < 64; ks += 16) {
            uint32_t a[2][4];
            #pragma unroll
            for (int mt = 0; mt < 2; mt++) {
                uint32_t ad = stA + aOff + (uint32_t)(((mt * 16 * SROW) + ks) << 1);
                LDSM4(a[mt][0], a[mt][1], a[mt][2], a[mt][3], ad);
            }
            #pragma unroll
            for (int nf2 = 0; nf2 < 4; nf2++) {
                uint32_t bd = stB + bOff + (uint32_t)(((nf2 * 16 * SROW) + ks) << 1);
                uint32_t b0a, b1a, b0b, b1b;
                LDSM4(b0a, b1a, b0b, b1b, bd);
                mma_f16(acc[0][2 * nf2],     a[0], b0a, b1a);
                mma_f16(acc[1][2 * nf2],     a[1], b0a, b1a);
                mma_f16(acc[0][2 * nf2 + 1], a[0], b0b, b1b);
                mma_f16(acc[1][2 * nf2 + 1], a[1], b0b, b1b);
            }
        }
    }

    // epilogue
    #pragma unroll
    for (int mt = 0; mt < 2; mt++) {
        int r0 = m0 + wm0 + mt * 16 + g;
        float mv0 = mask[bb * CC + (r0 & 1023)] ? 1.f : 0.f;
        float mv1 = mask[bb * CC + ((r0 + 8) & 1023)] ? 1.f : 0.f;
        #pragma unroll
        for (int nf = 0; nf < 8; nf++) {
            int col = n0 + wn0 + nf * 8 + 2 * t4;
            float bz0 = bias[col], bz1 = bias[col + 1];
            float v00 = (acc[mt][nf][0] + bz0) * mv0;
            float v01 = (acc[mt][nf][1] + bz1) * mv0;
            float v10 = (acc[mt][nf][2] + bz0) * mv1;
            float v11 = (acc[mt][nf][3] + bz1) * mv1;
            size_t o0 = (size_t)r0 * FF + col;
            size_t o1 = (size_t)(r0 + 8) * FF + col;
            if (MODE == 0) {
                *(__half2*)(g_h16 + o0) = __floats2half2_rn(v00, v01);
                *(__half2*)(g_h16 + o1) = __floats2half2_rn(v10, v11);
            } else {
                *(float2*)&out[o0] = make_float2(fmaxf(v00, 0.f), fmaxf(v01, 0.f));
                *(float2*)&out[o1] = make_float2(fmaxf(v10, 0.f), fmaxf(v11, 0.f));
            }
        }
    }
}

// =========================== launch ===========================
extern "C" void kernel_launch(void* const* d_in, const int* in_sizes, int n_in,
                              void* d_out, int out_size)
{
    const float* ctx = (const float*)d_in[0];
    const float* qst = (const float*)d_in[1];
    const int*   mask = (const int*)d_in[2];     // bool promoted to int32
    const float* wq = (const float*)d_in[3];
    const float* wc = (const float*)d_in[4];
    const float* wm = (const float*)d_in[5];
    const float* W1 = (const float*)d_in[6];
    const float* b1 = (const float*)d_in[7];
    const float* W2 = (const float*)d_in[8];
    const float* b2 = (const float*)d_in[9];
    float* out = (float*)d_out;

    __half *w1, *w2, *a16, *h16;
    cudaGetSymbolAddress((void**)&w1,  g_w1);
    cudaGetSymbolAddress((void**)&w2,  g_w2);
    cudaGetSymbolAddress((void**)&a16, g_a16);
    cudaGetSymbolAddress((void**)&h16, g_h16);

    cudaFuncSetAttribute(k_attn, cudaFuncAttributeMaxDynamicSharedMemorySize, K1_SMEM_BYTES);
    cudaFuncSetAttribute(k_gemm<0>, cudaFuncAttributeMaxDynamicSharedMemorySize, GEMM_SMEM);
    cudaFuncSetAttribute(k_gemm<1>, cudaFuncAttributeMaxDynamicSharedMemorySize, GEMM_SMEM);

    k_cvtw<<<FF * FF / 4 / 256, 256>>>(W1, w1);
    k_cvtw<<<FF * FF / 4 / 256, 256>>>(W2, w2);

    int nwarps = BB * QQ + BB * CC;
    k_dots<<<(nwarps + 7) / 8, 256>>>(qst, ctx, wq, wc);
    k_attn<<<dim3(CC / 128, BB), 256, K1_SMEM_BYTES>>>(ctx, qst, wm);
    k_q2c<<<BB, 256>>>(ctx);
    k_build_seg3<<<MM * 64 / 256, 256>>>(ctx);

    k_gemm<0><<<dim3(MM / 128, FF / 128), 256, GEMM_SMEM>>>(a16, w1, b1, mask, nullptr);
    k_gemm<1><<<dim3(MM / 128, FF / 128), 256, GEMM_SMEM>>>(h16, w2, b2, mask, out);
}